// round 15
// baseline (speedup 1.0000x reference)
#include <cuda_runtime.h>

// Problem shape (fixed by the reference setup_inputs):
//   template:    (5, 8, 2)  float32
//   projections: (5000, 8, 2) float32
// Output: concat( w_sel (5000,5,8,3) f32 , indices (5000,5,8,3) -> float )
static constexpr int V  = 5000;
static constexpr int R  = 5;
static constexpr int A  = 8;
static constexpr int NP = 8;
static constexpr int K  = 7;
static constexpr int NT = V * R * A;  // 200000 tasks

// Rank of combination (a<b<c) drawn from {0..6}; 35 total.
__host__ __device__ constexpr int tidx(int a, int b, int c) {
    int r = 0;
    for (int x = 0; x < a; x++) r += (6 - x) * (5 - x) / 2;
    for (int y = a + 1; y < b; y++) r += (6 - y);
    r += c - b - 1;
    return r;
}

// Bits of the 5 triples containing pair (i<j).
__host__ __device__ constexpr unsigned long long pair_B(int i, int j) {
    unsigned long long b = 0;
    for (int k = 0; k < 7; k++) {
        if (k == i || k == j) continue;
        int a = k < i ? k : i;
        int c = k > j ? k : j;
        int m = (k < i) ? i : ((k < j) ? k : j);
        b |= 1ull << tidx(a, m, c);
    }
    return b;
}
// Bits where the permutation (i,k,j)->(i,j,k-position) is odd: i<k<j.
__host__ __device__ constexpr unsigned long long pair_P(int i, int j) {
    unsigned long long p = 0;
    for (int k = i + 1; k < j; k++) p |= 1ull << tidx(i, k, j);
    return p;
}

__global__ __launch_bounds__(128, 8)
void bc_kernel(const float* __restrict__ tmpl,
               const float* __restrict__ proj,
               float* __restrict__ out)
{
    int task = blockIdx.x * blockDim.x + threadIdx.x;
    if (task >= NT) return;

    int v  = task / (R * A);
    int ra = task - v * (R * A);

    float tx = tmpl[2 * ra + 0];
    float ty = tmpl[2 * ra + 1];

    // Load projection row (8 points, vectorized)
    float px[NP], py[NP];
    const float4* p4 = reinterpret_cast<const float4*>(proj + v * NP * 2);
    {
        float4 q;
        q = p4[0]; px[0] = q.x; py[0] = q.y; px[1] = q.z; py[1] = q.w;
        q = p4[1]; px[2] = q.x; py[2] = q.y; px[3] = q.z; py[3] = q.w;
        q = p4[2]; px[4] = q.x; py[4] = q.y; px[5] = q.z; py[5] = q.w;
        q = p4[3]; px[6] = q.x; py[6] = q.y; px[7] = q.z; py[7] = q.w;
    }

    // Packed keys: squared distance bits (order == norm order for non-negative
    // floats compared as unsigned) with the original index in the 3 LSBs so
    // min() reproduces jnp.argsort's stable tie-break.
    unsigned key[NP];
    #pragma unroll
    for (int k = 0; k < NP; k++) {
        float dx = tx - px[k];
        float dy = ty - py[k];
        float sq = fmaf(dx, dx, dy * dy);
        key[k] = (__float_as_uint(sq) & ~7u) | (unsigned)k;
    }

    // min1/min2 tournament (closest + second-closest). Only the closest
    // (always) and second-closest (ref's default when nothing is valid)
    // depend on sort order; everything else is order-invariant.
    unsigned m1, m2;
    {
        unsigned a1 = umin(key[0], key[1]), a2 = umax(key[0], key[1]);
        unsigned b1 = umin(key[2], key[3]), b2 = umax(key[2], key[3]);
        unsigned c1_ = umin(key[4], key[5]), c2_ = umax(key[4], key[5]);
        unsigned d1 = umin(key[6], key[7]), d2 = umax(key[6], key[7]);
        unsigned e1 = umin(a1, b1);
        unsigned e2 = umin(umax(a1, b1), umin(a2, b2));
        unsigned f1 = umin(c1_, d1);
        unsigned f2 = umin(umax(c1_, d1), umin(c2_, d2));
        m1 = umin(e1, f1);
        m2 = umin(umax(e1, f1), umin(e2, f2));
    }
    int id0 = (int)(m1 & 7u);
    int id1 = (int)(m2 & 7u);

    // Extract closest point via 3-level mux on id0 bits
    float cx, cy;
    {
        bool s0 = (id0 & 1), s1 = (id0 & 2), s2 = (id0 & 4);
        float x01 = s0 ? px[1] : px[0], x23 = s0 ? px[3] : px[2];
        float x45 = s0 ? px[5] : px[4], x67 = s0 ? px[7] : px[6];
        float y01 = s0 ? py[1] : py[0], y23 = s0 ? py[3] : py[2];
        float y45 = s0 ? py[5] : py[4], y67 = s0 ? py[7] : py[6];
        float x03 = s1 ? x23 : x01, x47 = s1 ? x67 : x45;
        float y03 = s1 ? y23 : y01, y47 = s1 ? y67 : y45;
        cx = s2 ? x47 : x03;
        cy = s2 ? y47 : y03;
    }

    // Compact the 7 others in ORIGINAL index order (slot n -> original id
    // n + (n >= id0)), and lift: q_m = (o-c, |o|^2-|c|^2).
    // Reference det(i,j,k) == -[q_i, q_j, q_k] (triple product).
    float sc  = fmaf(cx, cx, cy * cy);
    float v2x = tx - cx, v2y = ty - cy;

    float qx[K], qy[K], qs[K], d00[K], d02[K];
    #pragma unroll
    for (int n = 0; n < K; n++) {
        bool ge = (n >= id0);
        float ox = ge ? px[n + 1] : px[n];
        float oy = ge ? py[n + 1] : py[n];
        qx[n]  = ox - cx;
        qy[n]  = oy - cy;
        qs[n]  = fmaf(ox, ox, oy * oy) - sc;
        d00[n] = fmaf(qx[n], qx[n], qy[n] * qy[n]);
        d02[n] = fmaf(qx[n], v2x, qy[n] * v2y);
    }

    // Sign mask of all 35 triple products T(a<b<c) = [q_a, q_b, q_c].
    // Only the SIGNS are ever consumed (validity is det<=0 / det>=0 tests),
    // so no T values are materialized: bit t of (mlo,mhi) = 1 iff T_t < 0.
    unsigned mlo = 0, mhi = 0;
    #pragma unroll
    for (int a = 0; a < K - 1; a++) {
        #pragma unroll
        for (int b = a + 1; b < K - 1; b++) {   // b <= 5: some c > b exists
            float crx = fmaf(qy[a], qs[b], -qs[a] * qy[b]);
            float cry = fmaf(qs[a], qx[b], -qx[a] * qs[b]);
            float crz = fmaf(qx[a], qy[b], -qy[a] * qx[b]);
            #pragma unroll
            for (int c = b + 1; c < K; c++) {
                float t = fmaf(crx, qx[c], fmaf(cry, qy[c], crz * qs[c]));
                unsigned sb = __float_as_uint(t) >> 31;
                int idx = tidx(a, b, c);
                if (idx < 32) mlo |= sb << idx;
                else          mhi |= sb << (idx - 32);
            }
        }
    }

    const float INF = __int_as_float(0x7f800000);
    float best = INF;
    float wAs = 0.f, wBs = 0.f;
    int code = 0;

    // Per UNORDERED pair: weights/score identical for both orders
    // (w2(i,j)==w1(j,i)); incircle dets are exact negations. Validity is
    // pure bit logic on the sign mask with compile-time constants:
    //   m_k sign = T-sign XOR (i<k<j)  ->  X = (M ^ P) & B
    //   c1 (order i,j): all m_k >= 0  <=>  X == 0
    //   c2 (order j,i): all m_k <= 0  <=>  X == B
    #pragma unroll
    for (int i = 0; i < K; i++) {
        #pragma unroll
        for (int j = i + 1; j < K; j++) {
            float d01   = fmaf(qx[i], qx[j], qy[i] * qy[j]);
            float denom = fmaf(d00[i], d00[j], -d01 * d01);
            float inv   = __fdividef(1.0f, denom);
            float nA = fmaf(d00[j], d02[i], -d01 * d02[j]);  // -> w2 of (i,j)
            float nB = fmaf(d00[i], d02[j], -d01 * d02[i]);  // -> w1 of (i,j)
            float wA = nA * inv;
            float wB = nB * inv;
            float w0 = 1.0f - wA - wB;
            bool wpos = (w0 > 0.f) && (wA > 0.f) && (wB > 0.f);  // NaN -> false
            // wpos => all weights positive => max(w^2) == (max w)^2
            float wmax = fmaxf(w0, fmaxf(wA, wB));
            float s = wmax * wmax;

            const unsigned long long Bm = pair_B(i, j);
            const unsigned long long Pm = pair_P(i, j);
            const unsigned Blo = (unsigned)Bm, Bhi = (unsigned)(Bm >> 32);
            const unsigned Plo = (unsigned)Pm, Phi = (unsigned)(Pm >> 32);
            unsigned xlo = (mlo ^ Plo) & Blo;
            unsigned xhi = (mhi ^ Phi) & Bhi;
            bool c1 = wpos && ((xlo | xhi) == 0u);
            bool c2 = wpos && (xlo == Blo) && (xhi == Bhi);
            // s is non-NaN whenever (c1|c2); strict < == first-occurrence argmin
            if ((c1 || c2) && (s < best)) {
                best = s;
                wAs  = wA;
                wBs  = wB;
                code = c1 ? ((i << 3) | j) : ((j << 3) | i);
            }
        }
    }

    bool has = best < INF;
    int row = code >> 3, col = code & 7;
    bool fwd = row < col;          // true <=> orientation c1 was selected
    float b0 = 1.0f - wAs - wBs;
    float b1 = fwd ? wAs : wBs;    // w2 of selected ordered pair
    float b2 = fwd ? wBs : wAs;    // w1 of selected ordered pair

    int bn1 = has ? (row + (row >= id0 ? 1 : 0)) : id1;
    int bn2 = has ? (col + (col >= id0 ? 1 : 0)) : id1;

    out[3 * task + 0] = has ? b0 : 0.f;
    out[3 * task + 1] = has ? b1 : 0.f;
    out[3 * task + 2] = has ? b2 : 0.f;

    float* io = out + 3 * NT;
    io[3 * task + 0] = (float)id0;
    io[3 * task + 1] = (float)bn1;
    io[3 * task + 2] = (float)bn2;
}

extern "C" void kernel_launch(void* const* d_in, const int* in_sizes, int n_in,
                              void* d_out, int out_size)
{
    const float* tmpl = (const float*)d_in[0];
    const float* proj = (const float*)d_in[1];
    float* out = (float*)d_out;

    const int threads = 128;
    const int blocks  = (NT + threads - 1) / threads;
    bc_kernel<<<blocks, threads>>>(tmpl, proj, out);
}